// round 1
// baseline (speedup 1.0000x reference)
#include <cuda_runtime.h>
#include <math.h>

// Depthwise conv1d, K=7, 'same' padding, softmax over taps.
// x: (B, C, T) fp32; weight: (H, 1, 7) fp32; head for channel c is c % H.
// out[b,c,t] = sum_k softmax(w[h])[k] * x[b,c, t+k-3]

#define KSIZE 7
#define PAD   3
#define TILE  1024
#define THREADS 256

__device__ float g_w[1024];  // softmaxed weights, H*7 used

__global__ void softmax_weights_kernel(const float* __restrict__ w, int H) {
    int h = threadIdx.x + blockIdx.x * blockDim.x;
    if (h < H) {
        float v[KSIZE];
        float m = -1e30f;
        #pragma unroll
        for (int k = 0; k < KSIZE; k++) {
            v[k] = w[h * KSIZE + k];
            m = fmaxf(m, v[k]);
        }
        float s = 0.f;
        #pragma unroll
        for (int k = 0; k < KSIZE; k++) {
            v[k] = expf(v[k] - m);
            s += v[k];
        }
        float inv = 1.f / s;
        #pragma unroll
        for (int k = 0; k < KSIZE; k++) {
            g_w[h * KSIZE + k] = v[k] * inv;
        }
    }
}

__global__ __launch_bounds__(THREADS)
void lconv1d_kernel(const float* __restrict__ x, float* __restrict__ out,
                    int T, int C, int H) {
    __shared__ float s[TILE + 2 * PAD];
    __shared__ float sw[KSIZE];

    const int row = blockIdx.y;              // b*C + c
    const int t0  = blockIdx.x * TILE;
    const long base = (long)row * T;
    const int tid = threadIdx.x;
    const int p = tid * 4;

    if (tid < KSIZE) {
        int h = (row % C) % H;
        sw[tid] = g_w[h * KSIZE + tid];
    }

    // Main tile: float4 global load, scalar shared stores (shifted by PAD)
    {
        const float4 v = *reinterpret_cast<const float4*>(x + base + t0 + p);
        s[p + PAD + 0] = v.x;
        s[p + PAD + 1] = v.y;
        s[p + PAD + 2] = v.z;
        s[p + PAD + 3] = v.w;
    }

    // Halos with zero padding at row boundaries
    if (tid < PAD) {
        int t = t0 - PAD + tid;
        s[tid] = (t >= 0) ? x[base + t] : 0.f;
    } else if (tid >= THREADS - PAD) {
        int j = tid - (THREADS - PAD);       // 0..2
        int t = t0 + TILE + j;
        s[TILE + PAD + j] = (t < T) ? x[base + t] : 0.f;
    }

    __syncthreads();

    const float w0 = sw[0], w1 = sw[1], w2 = sw[2], w3 = sw[3],
                w4 = sw[4], w5 = sw[5], w6 = sw[6];

    // s[p .. p+11], 16B-aligned shared vector loads (p % 4 == 0)
    const float4 a = *reinterpret_cast<const float4*>(&s[p]);
    const float4 b = *reinterpret_cast<const float4*>(&s[p + 4]);
    const float4 c = *reinterpret_cast<const float4*>(&s[p + 8]);

    float4 r;
    r.x = w0*a.x + w1*a.y + w2*a.z + w3*a.w + w4*b.x + w5*b.y + w6*b.z;
    r.y = w0*a.y + w1*a.z + w2*a.w + w3*b.x + w4*b.y + w5*b.z + w6*b.w;
    r.z = w0*a.z + w1*a.w + w2*b.x + w3*b.y + w4*b.z + w5*b.w + w6*c.x;
    r.w = w0*a.w + w1*b.x + w2*b.y + w3*b.z + w4*b.w + w5*c.x + w6*c.y;

    *reinterpret_cast<float4*>(out + base + t0 + p) = r;
}

extern "C" void kernel_launch(void* const* d_in, const int* in_sizes, int n_in,
                              void* d_out, int out_size) {
    const float* x = (const float*)d_in[0];
    const float* w = (const float*)d_in[1];
    float* out = (float*)d_out;

    const int H = in_sizes[1] / KSIZE;   // 16
    const int T = 4096;                  // fixed problem shape
    const int rows = in_sizes[0] / T;    // B*C = 16384
    const int C = 1024;

    softmax_weights_kernel<<<1, 32>>>(w, H);

    dim3 grid(T / TILE, rows);
    lconv1d_kernel<<<grid, THREADS>>>(x, out, T, C, H);
}

// round 2
// speedup vs baseline: 1.1988x; 1.1988x over previous
#include <cuda_runtime.h>
#include <math.h>

// Depthwise conv1d, K=7, 'same' padding, softmax over taps.
// x: (B, C, T) fp32; weight: (H, 1, 7); head for channel c is c % H (H=16).

#define KSIZE 7
#define TILE 2048
#define HALF (TILE / 2)
#define THREADS 256
#define SHIFT 4   // s[SHIFT + i] = x[t0 + i]; halo lives at s[1..3]

__device__ float g_w[128];  // softmaxed weights, H*7 used (H<=16)

__global__ void softmax_weights_kernel(const float* __restrict__ w, int H) {
    int h = threadIdx.x;
    if (h < H) {
        float v[KSIZE];
        float m = -1e30f;
        #pragma unroll
        for (int k = 0; k < KSIZE; k++) {
            v[k] = w[h * KSIZE + k];
            m = fmaxf(m, v[k]);
        }
        float s = 0.f;
        #pragma unroll
        for (int k = 0; k < KSIZE; k++) {
            v[k] = expf(v[k] - m);
            s += v[k];
        }
        float inv = 1.f / s;
        #pragma unroll
        for (int k = 0; k < KSIZE; k++) {
            g_w[h * KSIZE + k] = v[k] * inv;
        }
    }
}

__global__ __launch_bounds__(THREADS)
void lconv1d_kernel(const float* __restrict__ x, float* __restrict__ out,
                    int T) {
    __shared__ float s[TILE + 2 * SHIFT];

    const int row = blockIdx.y;               // b*C + c
    const int t0  = blockIdx.x * TILE;
    const size_t base = (size_t)row * T + t0;
    const int tid = threadIdx.x;
    const int p0 = tid * 4;
    const int p1 = p0 + HALF;

    // Two independent main-tile loads per thread (MLP=2), aligned STS.128.
    const float4 v0 = *reinterpret_cast<const float4*>(x + base + p0);
    const float4 v1 = *reinterpret_cast<const float4*>(x + base + p1);
    *reinterpret_cast<float4*>(&s[SHIFT + p0]) = v0;
    *reinterpret_cast<float4*>(&s[SHIFT + p1]) = v1;

    // Halos (3 left, 3 right) with zero padding at row boundaries.
    if (tid < 3) {
        int tl = t0 - 3 + tid;
        s[1 + tid] = (tl >= 0) ? x[base - 3 + tid] : 0.f;
        int tr = t0 + TILE + tid;
        s[SHIFT + TILE + tid] = (tr < T) ? x[base + TILE + tid] : 0.f;
    }

    // Weights: warp-uniform loads, overlap with the barrier.
    const int h = row & 15;  // C=1024 is a multiple of H=16
    const float w0 = g_w[h * KSIZE + 0];
    const float w1 = g_w[h * KSIZE + 1];
    const float w2 = g_w[h * KSIZE + 2];
    const float w3 = g_w[h * KSIZE + 3];
    const float w4 = g_w[h * KSIZE + 4];
    const float w5 = g_w[h * KSIZE + 5];
    const float w6 = g_w[h * KSIZE + 6];

    __syncthreads();

    // Chunk 0: outputs [p0 .. p0+3]. Middle float4 == v0 (register reuse).
    {
        const float4 a = *reinterpret_cast<const float4*>(&s[p0]);
        const float4 b = v0;
        const float4 c = *reinterpret_cast<const float4*>(&s[p0 + 8]);
        float4 r;
        r.x = w0*a.y + w1*a.z + w2*a.w + w3*b.x + w4*b.y + w5*b.z + w6*b.w;
        r.y = w0*a.z + w1*a.w + w2*b.x + w3*b.y + w4*b.z + w5*b.w + w6*c.x;
        r.z = w0*a.w + w1*b.x + w2*b.y + w3*b.z + w4*b.w + w5*c.x + w6*c.y;
        r.w = w0*b.x + w1*b.y + w2*b.z + w3*b.w + w4*c.x + w5*c.y + w6*c.z;
        *reinterpret_cast<float4*>(out + base + p0) = r;
    }

    // Chunk 1: outputs [p1 .. p1+3]. Middle float4 == v1.
    {
        const float4 a = *reinterpret_cast<const float4*>(&s[p1]);
        const float4 b = v1;
        const float4 c = *reinterpret_cast<const float4*>(&s[p1 + 8]);
        float4 r;
        r.x = w0*a.y + w1*a.z + w2*a.w + w3*b.x + w4*b.y + w5*b.z + w6*b.w;
        r.y = w0*a.z + w1*a.w + w2*b.x + w3*b.y + w4*b.z + w5*b.w + w6*c.x;
        r.z = w0*a.w + w1*b.x + w2*b.y + w3*b.z + w4*b.w + w5*c.x + w6*c.y;
        r.w = w0*b.x + w1*b.y + w2*b.z + w3*b.w + w4*c.x + w5*c.y + w6*c.z;
        *reinterpret_cast<float4*>(out + base + p1) = r;
    }
}

extern "C" void kernel_launch(void* const* d_in, const int* in_sizes, int n_in,
                              void* d_out, int out_size) {
    const float* x = (const float*)d_in[0];
    const float* w = (const float*)d_in[1];
    float* out = (float*)d_out;

    const int H = in_sizes[1] / KSIZE;   // 16
    const int T = 4096;                  // fixed problem shape
    const int rows = in_sizes[0] / T;    // B*C = 16384

    softmax_weights_kernel<<<1, 32>>>(w, H);

    dim3 grid(T / TILE, rows);
    lconv1d_kernel<<<grid, THREADS>>>(x, out, T);
}

// round 3
// speedup vs baseline: 1.2073x; 1.0070x over previous
#include <cuda_runtime.h>
#include <math.h>

// Depthwise conv1d, K=7, 'same' padding, softmax over taps — fused single kernel.
// x: (B, C, T) fp32; weight: (H, 1, 7); head for channel c is c % H (H=16).
// One block = one full row of T=4096 (whole-row tile: no inter-tile halos).

#define KSIZE 7
#define TILE 4096
#define THREADS 256
#define CHUNK (TILE / THREADS / 4)   // 4 float4 chunks per thread
#define Q (TILE / 4)                 // 1024: element stride between chunks
#define SHIFT 4                      // s[SHIFT + i] = x[i]; zeros at s[1..3]

__global__ __launch_bounds__(THREADS)
void lconv1d_fused_kernel(const float* __restrict__ x,
                          const float* __restrict__ wraw,
                          float* __restrict__ out) {
    __shared__ float s[SHIFT + TILE + 3];
    __shared__ float sw[KSIZE];

    const int row = blockIdx.x;               // b*C + c
    const size_t base = (size_t)row * TILE;
    const int tid = threadIdx.x;
    const int p = tid * 4;

    // Main tile: 4 independent float4 loads per thread (MLP=4), aligned STS.128.
    float4 v0 = *reinterpret_cast<const float4*>(x + base + p);
    float4 v1 = *reinterpret_cast<const float4*>(x + base + p + Q);
    float4 v2 = *reinterpret_cast<const float4*>(x + base + p + 2 * Q);
    float4 v3 = *reinterpret_cast<const float4*>(x + base + p + 3 * Q);
    *reinterpret_cast<float4*>(&s[SHIFT + p])         = v0;
    *reinterpret_cast<float4*>(&s[SHIFT + p + Q])     = v1;
    *reinterpret_cast<float4*>(&s[SHIFT + p + 2 * Q]) = v2;
    *reinterpret_cast<float4*>(&s[SHIFT + p + 3 * Q]) = v3;

    // Zero padding at both row ends ('same' padding, PAD=3).
    if (tid < 3) {
        s[1 + tid] = 0.f;
        s[SHIFT + TILE + tid] = 0.f;
    }

    // Fused softmax over the 7 taps of this row's head (threads 0..6).
    if (tid < KSIZE) {
        const int h = row & 15;               // C=1024 multiple of H=16
        float v[KSIZE];
        float m = -1e30f;
        #pragma unroll
        for (int k = 0; k < KSIZE; k++) {
            v[k] = __ldg(&wraw[h * KSIZE + k]);
            m = fmaxf(m, v[k]);
        }
        float sum = 0.f;
        #pragma unroll
        for (int k = 0; k < KSIZE; k++) sum += expf(v[k] - m);
        sw[tid] = expf(v[tid] - m) / sum;
    }

    __syncthreads();

    const float w0 = sw[0], w1 = sw[1], w2 = sw[2], w3 = sw[3],
                w4 = sw[4], w5 = sw[5], w6 = sw[6];

    // 4 chunks; middle float4 of each window comes from the load registers.
    #pragma unroll
    for (int i = 0; i < 4; i++) {
        const int q = p + i * Q;
        const float4 b = (i == 0) ? v0 : (i == 1) ? v1 : (i == 2) ? v2 : v3;
        const float4 a = *reinterpret_cast<const float4*>(&s[q]);       // [q-4 .. q-1] (+SHIFT-4)
        const float4 c = *reinterpret_cast<const float4*>(&s[q + 8]);   // [q+4 .. q+7]
        float4 r;
        r.x = w0*a.y + w1*a.z + w2*a.w + w3*b.x + w4*b.y + w5*b.z + w6*b.w;
        r.y = w0*a.z + w1*a.w + w2*b.x + w3*b.y + w4*b.z + w5*b.w + w6*c.x;
        r.z = w0*a.w + w1*b.x + w2*b.y + w3*b.z + w4*b.w + w5*c.x + w6*c.y;
        r.w = w0*b.x + w1*b.y + w2*b.z + w3*b.w + w4*c.x + w5*c.y + w6*c.z;
        *reinterpret_cast<float4*>(out + base + q) = r;
    }
}

extern "C" void kernel_launch(void* const* d_in, const int* in_sizes, int n_in,
                              void* d_out, int out_size) {
    const float* x = (const float*)d_in[0];
    const float* w = (const float*)d_in[1];
    float* out = (float*)d_out;

    const int T = TILE;                  // 4096, fixed problem shape
    const int rows = in_sizes[0] / T;    // B*C = 16384

    lconv1d_fused_kernel<<<rows, THREADS>>>(x, w, out);
}